// round 16
// baseline (speedup 1.0000x reference)
#include <cuda_runtime.h>
#include <math.h>

#define B_ 2
#define L_ 256
#define D_ 256
#define DI_ 512
#define N_ 32
#define R_ 16
#define K_ 4
#define M_ 16
#define NB_ 7
#define BL_ 512           // B_*L_
#define DOUT_ 76416

// ---------------- scratch (device globals; no allocation allowed) -------------
__device__ float g_resid[BL_ * D_];
__device__ float g_ln[BL_ * D_];
__device__ float g_hid[BL_ * D_];
__device__ float g_xz[BL_ * 2 * DI_];
__device__ float g_xc[BL_ * DI_];
__device__ float g_dbl[BL_ * (R_ + N_)];
__device__ float g_dt[BL_ * DI_];
__device__ float g_y[BL_ * DI_];
__device__ float g_gate[BL_ * DI_];
__device__ float g_xr[B_ * M_ * DI_];
__device__ float g_xi[B_ * M_ * DI_];

__device__ __forceinline__ float silu_f(float v) {
    return v / (1.0f + expf(-v));
}

__device__ __forceinline__ unsigned f2tf(float f) {
    unsigned u; asm("cvt.rna.tf32.f32 %0, %1;" : "=r"(u) : "f"(f)); return u;
}

__device__ __forceinline__ void mma8(float* d, const unsigned* a, const unsigned* b) {
    asm volatile("mma.sync.aligned.m16n8k8.row.col.f32.tf32.tf32.f32 "
        "{%0,%1,%2,%3},{%4,%5,%6,%7},{%8,%9},{%0,%1,%2,%3};"
        : "+f"(d[0]), "+f"(d[1]), "+f"(d[2]), "+f"(d[3])
        : "r"(a[0]), "r"(a[1]), "r"(a[2]), "r"(a[3]), "r"(b[0]), "r"(b[1]));
}

__device__ __forceinline__ void cp16(void* dst, const void* src) {
    unsigned d = (unsigned)__cvta_generic_to_shared(dst);
    asm volatile("cp.async.ca.shared.global [%0],[%1],16;" :: "r"(d), "l"(src));
}

// ---------------- prenorm: residual update + layernorm ----------------------
__global__ void k_prenorm(const float* __restrict__ xin,
                          const float* __restrict__ lnw,
                          const float* __restrict__ lnb,
                          int is_first) {
    __shared__ float ws[8];
    __shared__ float s_mean, s_rstd;
    int t = blockIdx.x, i = threadIdx.x;
    int warp = i >> 5, lane = i & 31;
    float r = is_first ? xin[t * D_ + i] : (g_resid[t * D_ + i] + g_hid[t * D_ + i]);
    g_resid[t * D_ + i] = r;
    float s = r;
#pragma unroll
    for (int o = 16; o > 0; o >>= 1) s += __shfl_xor_sync(0xffffffffu, s, o);
    if (lane == 0) ws[warp] = s;
    __syncthreads();
    if (warp == 0) {
        float v = (lane < 8) ? ws[lane] : 0.f;
#pragma unroll
        for (int o = 4; o > 0; o >>= 1) v += __shfl_xor_sync(0xffffffffu, v, o);
        if (lane == 0) s_mean = v * (1.0f / D_);
    }
    __syncthreads();
    float dv = r - s_mean;
    s = dv * dv;
#pragma unroll
    for (int o = 16; o > 0; o >>= 1) s += __shfl_xor_sync(0xffffffffu, s, o);
    if (lane == 0) ws[warp] = s;
    __syncthreads();
    if (warp == 0) {
        float v = (lane < 8) ? ws[lane] : 0.f;
#pragma unroll
        for (int o = 4; o > 0; o >>= 1) v += __shfl_xor_sync(0xffffffffu, v, o);
        if (lane == 0) s_rstd = rsqrtf(v * (1.0f / D_) + 1e-5f);
    }
    __syncthreads();
    g_ln[t * D_ + i] = dv * s_rstd * lnw[i] + lnb[i];
}

// ---------------- tf32 tensor-core NT GEMM, double-buffered cp.async --------
// C[m,n] = sum_k A[m,k] * W[n,k]. M%BM==0, N%BN==0, K%16==0.
template<int BM, int BN, int WM, int WN>
__global__ __launch_bounds__(256) void gemm_db(const float* __restrict__ A,
                                               const float* __restrict__ W,
                                               float* __restrict__ C,
                                               int Nd, int Kd) {
    constexpr int TM = BM / WM;     // warp tile m
    constexpr int TN = BN / WN;     // warp tile n
    constexpr int MT = TM / 16;
    constexpr int NT = TN / 8;
    __shared__ float As[2][BM][20];
    __shared__ float Ws[2][BN][20];

    int tid = threadIdx.x;
    int warp = tid >> 5, lane = tid & 31;
    int g = lane >> 2, tg = lane & 3;
    int wm = warp / WN, wn = warp % WN;
    int m0 = blockIdx.y * BM, n0 = blockIdx.x * BN;

    float acc[MT][NT][4];
#pragma unroll
    for (int i = 0; i < MT; i++)
#pragma unroll
        for (int j = 0; j < NT; j++)
#pragma unroll
            for (int q = 0; q < 4; q++) acc[i][j][q] = 0.f;

    int ntile = Kd / 16;

#define LOAD_TILE(buf, kt)                                                     \
    {                                                                          \
        _Pragma("unroll")                                                      \
        for (int i = tid; i < BM * 4; i += 256) {                              \
            int row = i >> 2, kq = i & 3;                                      \
            cp16(&As[buf][row][kq * 4],                                        \
                 A + (size_t)(m0 + row) * Kd + (kt) + kq * 4);                 \
        }                                                                      \
        _Pragma("unroll")                                                      \
        for (int i = tid; i < BN * 4; i += 256) {                              \
            int row = i >> 2, kq = i & 3;                                      \
            cp16(&Ws[buf][row][kq * 4],                                        \
                 W + (size_t)(n0 + row) * Kd + (kt) + kq * 4);                 \
        }                                                                      \
        asm volatile("cp.async.commit_group;");                                \
    }

    LOAD_TILE(0, 0)

    for (int t = 0; t < ntile; t++) {
        if (t + 1 < ntile) {
            LOAD_TILE((t + 1) & 1, (t + 1) * 16)
        } else {
            asm volatile("cp.async.commit_group;");
        }
        asm volatile("cp.async.wait_group 1;");
        __syncthreads();
        int buf = t & 1;
#pragma unroll
        for (int kk = 0; kk < 16; kk += 8) {
            unsigned af[MT][4], bf[NT][2];
#pragma unroll
            for (int i = 0; i < MT; i++) {
                int m = wm * TM + i * 16;
                af[i][0] = f2tf(As[buf][m + g][kk + tg]);
                af[i][1] = f2tf(As[buf][m + g + 8][kk + tg]);
                af[i][2] = f2tf(As[buf][m + g][kk + tg + 4]);
                af[i][3] = f2tf(As[buf][m + g + 8][kk + tg + 4]);
            }
#pragma unroll
            for (int j = 0; j < NT; j++) {
                int n = wn * TN + j * 8;
                bf[j][0] = f2tf(Ws[buf][n + g][kk + tg]);
                bf[j][1] = f2tf(Ws[buf][n + g][kk + tg + 4]);
            }
#pragma unroll
            for (int i = 0; i < MT; i++)
#pragma unroll
                for (int j = 0; j < NT; j++)
                    mma8(acc[i][j], af[i], bf[j]);
        }
        __syncthreads();
    }
#undef LOAD_TILE

#pragma unroll
    for (int i = 0; i < MT; i++) {
        int row0 = m0 + wm * TM + i * 16 + g;
#pragma unroll
        for (int j = 0; j < NT; j++) {
            int col = n0 + wn * TN + j * 8 + 2 * tg;
            *(float2*)(C + (size_t)row0 * Nd + col) =
                make_float2(acc[i][j][0], acc[i][j][1]);
            *(float2*)(C + (size_t)(row0 + 8) * Nd + col) =
                make_float2(acc[i][j][2], acc[i][j][3]);
        }
    }
}

// ---------------- depthwise causal conv (K=4) + silu ------------------------
__global__ void k_conv(const float* __restrict__ cw, const float* __restrict__ cb) {
    int idx = blockIdx.x * 256 + threadIdx.x;   // over BL_*DI_
    int d = idx & (DI_ - 1);
    int bl = idx >> 9;
    int l = bl & (L_ - 1);
    int b0 = bl - l;
    float s = cb[d];
#pragma unroll
    for (int k = 0; k < K_; k++) {
        int lt = l - (K_ - 1) + k;
        if (lt >= 0) s += g_xz[(size_t)(b0 + lt) * (2 * DI_) + d] * cw[d * K_ + k];
    }
    g_xc[idx] = silu_f(s);
}

// ---------------- xproj: warp per (row, 4 outputs) --------------------------
// dbl[512,48] = xc[512,512] @ xw[48,512]^T.  6144 warps = 768 blocks x 256.
__global__ __launch_bounds__(256) void k_xproj(const float* __restrict__ W) {
    int warp = threadIdx.x >> 5, lane = threadIdx.x & 31;
    int task = blockIdx.x * 8 + warp;        // 0..6143
    int row = task / 12;
    int c0 = (task % 12) * 4;
    const float4* ap = (const float4*)(g_xc + (size_t)row * DI_);
    float4 av[4];
#pragma unroll
    for (int j = 0; j < 4; j++) av[j] = ap[j * 32 + lane];
    float acc[4];
#pragma unroll
    for (int c = 0; c < 4; c++) {
        const float4* wp = (const float4*)(W + (size_t)(c0 + c) * DI_);
        float s = 0.f;
#pragma unroll
        for (int j = 0; j < 4; j++) {
            float4 w = wp[j * 32 + lane];
            s += av[j].x * w.x + av[j].y * w.y + av[j].z * w.z + av[j].w * w.w;
        }
        acc[c] = s;
    }
#pragma unroll
    for (int c = 0; c < 4; c++)
#pragma unroll
        for (int o = 16; o > 0; o >>= 1)
            acc[c] += __shfl_xor_sync(0xffffffffu, acc[c], o);
    if (lane < 4)
        g_dbl[row * (R_ + N_) + c0 + lane] =
            (lane == 0) ? acc[0] : (lane == 1) ? acc[1] : (lane == 2) ? acc[2] : acc[3];
}

// ---------------- dt = softplus(dbl[:, :R] @ dt_w^T + dt_b) -----------------
__global__ void k_dt(const float* __restrict__ dtw, const float* __restrict__ dtb) {
    __shared__ float sd[R_];
    int blk = blockIdx.x;                 // 1024 = BL_ * 2
    int t = blk >> 1;
    int d = (blk & 1) * 256 + threadIdx.x;
    if (threadIdx.x < R_) sd[threadIdx.x] = g_dbl[t * (R_ + N_) + threadIdx.x];
    __syncthreads();
    float s = dtb[d];
#pragma unroll
    for (int r = 0; r < R_; r++) s = fmaf(sd[r], dtw[d * R_ + r], s);
    g_dt[t * DI_ + d] = (s > 20.f) ? s : log1pf(expf(s));
}

// ---------------- selective scan: warp per (b,d), lane = n ------------------
// chunk=8 register pipeline: prefetch next chunk's inputs, keep h-chain clean.
__global__ __launch_bounds__(128) void k_scan(const float* __restrict__ Alog,
                                              const float* __restrict__ Cm,
                                              const float* __restrict__ Dv) {
    __shared__ float sm[4][8 * 33];
    int warp = threadIdx.x >> 5;
    int lane = threadIdx.x & 31;
    int w = blockIdx.x * 4 + warp;       // 0..1023
    int n = lane;
    int b = w >> 9;
    int d = w & (DI_ - 1);
    float a = -expf(Alog[d * N_ + n]);
    float c = Cm[d * N_ + n];
    float Ddv = Dv[d];
    float h = 0.f;
    int base = b * L_ * DI_ + d;
    int bbase = b * L_ * (R_ + N_) + R_ + n;
    float* row = sm[warp];

    float dtv[8], xv[8], Bv[8];
#pragma unroll
    for (int j = 0; j < 8; j++) {
        dtv[j] = g_dt[base + j * DI_];
        xv[j]  = g_xc[base + j * DI_];
        Bv[j]  = g_dbl[bbase + j * (R_ + N_)];
    }

    for (int t0 = 0; t0 < L_; t0 += 8) {
        float ndt[8], nx[8], nB[8];
        if (t0 + 8 < L_) {
#pragma unroll
            for (int j = 0; j < 8; j++) {
                int t = t0 + 8 + j;
                ndt[j] = g_dt[base + t * DI_];
                nx[j]  = g_xc[base + t * DI_];
                nB[j]  = g_dbl[bbase + t * (R_ + N_)];
            }
        }
        float p[8];
#pragma unroll
        for (int j = 0; j < 8; j++) {
            float dA = __expf(dtv[j] * a);
            h = fmaf(dA, h, dtv[j] * Bv[j] * xv[j]);
            p[j] = h * c;
            if (n == 0) p[j] = fmaf(Ddv, xv[j], p[j]);
        }
#pragma unroll
        for (int j = 0; j < 8; j++) row[j * 33 + lane] = p[j];
        __syncwarp();
        if (lane < 8) {
            float s0 = 0.f, s1 = 0.f;
#pragma unroll
            for (int k = 0; k < 16; k++) {
                s0 += row[lane * 33 + k];
                s1 += row[lane * 33 + 16 + k];
            }
            g_y[base + (t0 + lane) * DI_] = s0 + s1;
        }
        __syncwarp();
#pragma unroll
        for (int j = 0; j < 8; j++) { dtv[j] = ndt[j]; xv[j] = nx[j]; Bv[j] = nB[j]; }
    }
}

// ---------------- 16-mode forward DFT along L, smem-tiled -------------------
// block = (b, 16-d chunk); 256 threads = 16 freq x 16 d. xc tile staged in smem.
__global__ __launch_bounds__(256) void k_dftf() {
    __shared__ float cs[L_], sn[L_];
    __shared__ float sx[L_ * 16];          // [t][dl], 16 KB
    int tid = threadIdx.x;
    int b = blockIdx.x >> 5;               // 0..1
    int d0 = (blockIdx.x & 31) * 16;
    {
        float ang = (6.283185307179586f / L_) * (float)tid;
        cs[tid] = cosf(ang);
        sn[tid] = sinf(ang);
    }
    int base = b * L_ * DI_ + d0;
    for (int i = tid; i < L_ * 16; i += 256) {
        int t = i >> 4, dl = i & 15;
        sx[i] = g_xc[base + t * DI_ + dl];
    }
    __syncthreads();
    int f = tid >> 4, dl = tid & 15;
    float ar = 0.f, ai = 0.f;
#pragma unroll 8
    for (int t = 0; t < L_; t++) {
        float x = sx[t * 16 + dl];
        int k = (f * t) & (L_ - 1);
        ar = fmaf(x, cs[k], ar);
        ai = fmaf(-x, sn[k], ai);
    }
    g_xr[(b * M_ + f) * DI_ + d0 + dl] = ar;
    g_xi[(b * M_ + f) * DI_ + d0 + dl] = ai;
}

// ---------------- fused inverse DFT + gate ----------------------------------
// idx over BL_*DI_; y = scan_y + irfft16; out = y * silu(z)
__global__ void k_dftig(const float* __restrict__ sr, const float* __restrict__ si) {
    __shared__ float cs[M_], sn[M_];
    int idx = blockIdx.x * 256 + threadIdx.x;
    int bl = idx >> 9;                    // (b*L + t), const per block
    int d = idx & (DI_ - 1);
    int t = bl & (L_ - 1);
    int b = bl >> 8;
    if (threadIdx.x < M_) {
        int kk = (threadIdx.x * t) & (L_ - 1);
        float ang = (6.283185307179586f / L_) * (float)kk;
        cs[threadIdx.x] = cosf(ang);
        sn[threadIdx.x] = sinf(ang);
    }
    __syncthreads();
    float acc = 0.f;
#pragma unroll
    for (int f = 0; f < M_; f++) {
        float xr = g_xr[(b * M_ + f) * DI_ + d];
        float xi = g_xi[(b * M_ + f) * DI_ + d];
        float wr = sr[d * M_ + f];
        float wi = si[d * M_ + f];
        float zr = xr * wr - xi * wi;
        float zi = xr * wi + xi * wr;
        float v = zr * cs[f] - zi * sn[f];
        acc += (f == 0) ? v : 2.f * v;
    }
    float y = g_y[idx] + acc * (1.0f / L_);
    float z = g_xz[(size_t)bl * (2 * DI_) + DI_ + d];
    g_gate[idx] = y * silu_f(z);
}

// ---------------- host driver ------------------------------------------------
static cudaStream_t s2;
static cudaEvent_t ev_fork, ev_join;
static bool s_init = false;

static void run_mixer(const float* in_w, const float* cw, const float* cb,
                      const float* xw, const float* dtw, const float* dtb,
                      const float* Al, const float* Cm, const float* Dv,
                      const float* sr, const float* si,
                      const float* ow, float* outC, int outN, int is_final,
                      float* p_ln, float* p_xz, float* p_gate) {
    // in_proj: [512,1024] = ln[512,256] @ in_w[1024,256]^T
    gemm_db<64, 64, 2, 4><<<dim3(2 * DI_ / 64, BL_ / 64), 256>>>(p_ln, in_w, p_xz, 2 * DI_, D_);
    k_conv<<<BL_ * DI_ / 256, 256>>>(cw, cb);
    // fork: forward DFT runs concurrently with xproj -> dt -> scan
    cudaEventRecord(ev_fork, 0);
    cudaStreamWaitEvent(s2, ev_fork, 0);
    k_dftf<<<B_ * 32, 256, 0, s2>>>();
    cudaEventRecord(ev_join, s2);
    k_xproj<<<768, 256>>>(xw);
    k_dt<<<BL_ * 2, 256>>>(dtw, dtb);
    k_scan<<<256, 128>>>(Al, Cm, Dv);
    cudaStreamWaitEvent(0, ev_join, 0);
    k_dftig<<<BL_ * DI_ / 256, 256>>>(sr, si);
    if (is_final) {
        gemm_db<128, 128, 2, 4><<<dim3(outN / 128, BL_ / 128), 256>>>(p_gate, ow, outC, outN, DI_);
    } else {
        gemm_db<32, 64, 2, 4><<<dim3(outN / 64, BL_ / 32), 256>>>(p_gate, ow, outC, outN, DI_);
    }
}

extern "C" void kernel_launch(void* const* d_in, const int* in_sizes, int n_in,
                              void* d_out, int out_size) {
    if (!s_init) {
        cudaStreamCreateWithFlags(&s2, cudaStreamNonBlocking);
        cudaEventCreateWithFlags(&ev_fork, cudaEventDisableTiming);
        cudaEventCreateWithFlags(&ev_join, cudaEventDisableTiming);
        s_init = true;
    }
    const float* x       = (const float*)d_in[0];
    const float* ln_w    = (const float*)d_in[1];
    const float* ln_b    = (const float*)d_in[2];
    const float* in_w    = (const float*)d_in[3];
    const float* conv_w  = (const float*)d_in[4];
    const float* conv_b  = (const float*)d_in[5];
    const float* xproj_w = (const float*)d_in[6];
    const float* dt_w    = (const float*)d_in[7];
    const float* dt_b    = (const float*)d_in[8];
    const float* A_log   = (const float*)d_in[9];
    const float* Cmat    = (const float*)d_in[10];
    const float* Dvec    = (const float*)d_in[11];
    const float* spec_r  = (const float*)d_in[12];
    const float* spec_i  = (const float*)d_in[13];
    const float* out_w   = (const float*)d_in[14];
    const float* fln_w   = (const float*)d_in[15];
    const float* fln_b   = (const float*)d_in[16];
    const float* f_in_w  = (const float*)d_in[17];
    const float* f_conv_w  = (const float*)d_in[18];
    const float* f_conv_b  = (const float*)d_in[19];
    const float* f_xproj_w = (const float*)d_in[20];
    const float* f_dt_w    = (const float*)d_in[21];
    const float* f_dt_b    = (const float*)d_in[22];
    const float* f_A_log   = (const float*)d_in[23];
    const float* f_Cmat    = (const float*)d_in[24];
    const float* f_Dvec    = (const float*)d_in[25];
    const float* f_spec_r  = (const float*)d_in[26];
    const float* f_spec_i  = (const float*)d_in[27];
    const float* f_out_w   = (const float*)d_in[28];

    float *p_ln, *p_xz, *p_gate, *p_hid;
    cudaGetSymbolAddress((void**)&p_ln, g_ln);
    cudaGetSymbolAddress((void**)&p_xz, g_xz);
    cudaGetSymbolAddress((void**)&p_gate, g_gate);
    cudaGetSymbolAddress((void**)&p_hid, g_hid);

    for (int i = 0; i < NB_; i++) {
        k_prenorm<<<BL_, D_>>>(x, ln_w + i * D_, ln_b + i * D_, (i == 0) ? 1 : 0);
        run_mixer(in_w + (size_t)i * 2 * DI_ * D_,
                  conv_w + (size_t)i * DI_ * K_,
                  conv_b + (size_t)i * DI_,
                  xproj_w + (size_t)i * (R_ + N_) * DI_,
                  dt_w + (size_t)i * DI_ * R_,
                  dt_b + (size_t)i * DI_,
                  A_log + (size_t)i * DI_ * N_,
                  Cmat + (size_t)i * DI_ * N_,
                  Dvec + (size_t)i * DI_,
                  spec_r + (size_t)i * DI_ * M_,
                  spec_i + (size_t)i * DI_ * M_,
                  out_w + (size_t)i * D_ * DI_,
                  p_hid, D_, 0,
                  p_ln, p_xz, p_gate);
    }
    // final block
    k_prenorm<<<BL_, D_>>>(x, fln_w, fln_b, 0);
    run_mixer(f_in_w, f_conv_w, f_conv_b, f_xproj_w, f_dt_w, f_dt_b,
              f_A_log, f_Cmat, f_Dvec, f_spec_r, f_spec_i,
              f_out_w, (float*)d_out, DOUT_, 1,
              p_ln, p_xz, p_gate);
}

// round 17
// speedup vs baseline: 1.5362x; 1.5362x over previous
#include <cuda_runtime.h>
#include <math.h>

#define B_ 2
#define L_ 256
#define D_ 256
#define DI_ 512
#define N_ 32
#define R_ 16
#define K_ 4
#define M_ 16
#define NB_ 7
#define BL_ 512           // B_*L_
#define DOUT_ 76416

// ---------------- scratch (device globals; no allocation allowed) -------------
__device__ float g_resid[BL_ * D_];
__device__ float g_ln[BL_ * D_];
__device__ float g_hid[BL_ * D_];
__device__ float g_xz[BL_ * 2 * DI_];
__device__ float g_xc[BL_ * DI_];
__device__ float g_dbl[BL_ * (R_ + N_)];
__device__ float g_dt[BL_ * DI_];
__device__ float g_y[BL_ * DI_];
__device__ float g_gate[BL_ * DI_];
__device__ float g_xr[B_ * M_ * DI_];
__device__ float g_xi[B_ * M_ * DI_];

__device__ __forceinline__ float silu_f(float v) {
    return v / (1.0f + expf(-v));
}

__device__ __forceinline__ unsigned f2tf(float f) {
    unsigned u; asm("cvt.rna.tf32.f32 %0, %1;" : "=r"(u) : "f"(f)); return u;
}

__device__ __forceinline__ void mma8(float* d, const unsigned* a, const unsigned* b) {
    asm volatile("mma.sync.aligned.m16n8k8.row.col.f32.tf32.tf32.f32 "
        "{%0,%1,%2,%3},{%4,%5,%6,%7},{%8,%9},{%0,%1,%2,%3};"
        : "+f"(d[0]), "+f"(d[1]), "+f"(d[2]), "+f"(d[3])
        : "r"(a[0]), "r"(a[1]), "r"(a[2]), "r"(a[3]), "r"(b[0]), "r"(b[1]));
}

__device__ __forceinline__ void cp16(void* dst, const void* src) {
    unsigned d = (unsigned)__cvta_generic_to_shared(dst);
    asm volatile("cp.async.ca.shared.global [%0],[%1],16;" :: "r"(d), "l"(src));
}

// ---------------- prenorm: residual update + layernorm ----------------------
__global__ void k_prenorm(const float* __restrict__ xin,
                          const float* __restrict__ lnw,
                          const float* __restrict__ lnb,
                          int is_first) {
    __shared__ float ws[8];
    __shared__ float s_mean, s_rstd;
    int t = blockIdx.x, i = threadIdx.x;
    int warp = i >> 5, lane = i & 31;
    float r = is_first ? xin[t * D_ + i] : (g_resid[t * D_ + i] + g_hid[t * D_ + i]);
    g_resid[t * D_ + i] = r;
    float s = r;
#pragma unroll
    for (int o = 16; o > 0; o >>= 1) s += __shfl_xor_sync(0xffffffffu, s, o);
    if (lane == 0) ws[warp] = s;
    __syncthreads();
    if (warp == 0) {
        float v = (lane < 8) ? ws[lane] : 0.f;
#pragma unroll
        for (int o = 4; o > 0; o >>= 1) v += __shfl_xor_sync(0xffffffffu, v, o);
        if (lane == 0) s_mean = v * (1.0f / D_);
    }
    __syncthreads();
    float dv = r - s_mean;
    s = dv * dv;
#pragma unroll
    for (int o = 16; o > 0; o >>= 1) s += __shfl_xor_sync(0xffffffffu, s, o);
    if (lane == 0) ws[warp] = s;
    __syncthreads();
    if (warp == 0) {
        float v = (lane < 8) ? ws[lane] : 0.f;
#pragma unroll
        for (int o = 4; o > 0; o >>= 1) v += __shfl_xor_sync(0xffffffffu, v, o);
        if (lane == 0) s_rstd = rsqrtf(v * (1.0f / D_) + 1e-5f);
    }
    __syncthreads();
    g_ln[t * D_ + i] = dv * s_rstd * lnw[i] + lnb[i];
}

// ---------------- tf32 tensor-core NT GEMM, double-buffered cp.async --------
// C[m,n] = sum_k A[m,k] * W[n,k]. M%BM==0, N%BN==0, K%16==0.
template<int BM, int BN, int WM, int WN>
__global__ __launch_bounds__(256) void gemm_db(const float* __restrict__ A,
                                               const float* __restrict__ W,
                                               float* __restrict__ C,
                                               int Nd, int Kd) {
    constexpr int TM = BM / WM;     // warp tile m
    constexpr int TN = BN / WN;     // warp tile n
    constexpr int MT = TM / 16;
    constexpr int NT = TN / 8;
    __shared__ float As[2][BM][20];
    __shared__ float Ws[2][BN][20];

    int tid = threadIdx.x;
    int warp = tid >> 5, lane = tid & 31;
    int g = lane >> 2, tg = lane & 3;
    int wm = warp / WN, wn = warp % WN;
    int m0 = blockIdx.y * BM, n0 = blockIdx.x * BN;

    float acc[MT][NT][4];
#pragma unroll
    for (int i = 0; i < MT; i++)
#pragma unroll
        for (int j = 0; j < NT; j++)
#pragma unroll
            for (int q = 0; q < 4; q++) acc[i][j][q] = 0.f;

    int ntile = Kd / 16;

#define LOAD_TILE(buf, kt)                                                     \
    {                                                                          \
        _Pragma("unroll")                                                      \
        for (int i = tid; i < BM * 4; i += 256) {                              \
            int row = i >> 2, kq = i & 3;                                      \
            cp16(&As[buf][row][kq * 4],                                        \
                 A + (size_t)(m0 + row) * Kd + (kt) + kq * 4);                 \
        }                                                                      \
        _Pragma("unroll")                                                      \
        for (int i = tid; i < BN * 4; i += 256) {                              \
            int row = i >> 2, kq = i & 3;                                      \
            cp16(&Ws[buf][row][kq * 4],                                        \
                 W + (size_t)(n0 + row) * Kd + (kt) + kq * 4);                 \
        }                                                                      \
        asm volatile("cp.async.commit_group;");                                \
    }

    LOAD_TILE(0, 0)

    for (int t = 0; t < ntile; t++) {
        if (t + 1 < ntile) {
            LOAD_TILE((t + 1) & 1, (t + 1) * 16)
        } else {
            asm volatile("cp.async.commit_group;");
        }
        asm volatile("cp.async.wait_group 1;");
        __syncthreads();
        int buf = t & 1;
#pragma unroll
        for (int kk = 0; kk < 16; kk += 8) {
            unsigned af[MT][4], bf[NT][2];
#pragma unroll
            for (int i = 0; i < MT; i++) {
                int m = wm * TM + i * 16;
                af[i][0] = f2tf(As[buf][m + g][kk + tg]);
                af[i][1] = f2tf(As[buf][m + g + 8][kk + tg]);
                af[i][2] = f2tf(As[buf][m + g][kk + tg + 4]);
                af[i][3] = f2tf(As[buf][m + g + 8][kk + tg + 4]);
            }
#pragma unroll
            for (int j = 0; j < NT; j++) {
                int n = wn * TN + j * 8;
                bf[j][0] = f2tf(Ws[buf][n + g][kk + tg]);
                bf[j][1] = f2tf(Ws[buf][n + g][kk + tg + 4]);
            }
#pragma unroll
            for (int i = 0; i < MT; i++)
#pragma unroll
                for (int j = 0; j < NT; j++)
                    mma8(acc[i][j], af[i], bf[j]);
        }
        __syncthreads();
    }
#undef LOAD_TILE

#pragma unroll
    for (int i = 0; i < MT; i++) {
        int row0 = m0 + wm * TM + i * 16 + g;
#pragma unroll
        for (int j = 0; j < NT; j++) {
            int col = n0 + wn * TN + j * 8 + 2 * tg;
            *(float2*)(C + (size_t)row0 * Nd + col) =
                make_float2(acc[i][j][0], acc[i][j][1]);
            *(float2*)(C + (size_t)(row0 + 8) * Nd + col) =
                make_float2(acc[i][j][2], acc[i][j][3]);
        }
    }
}

// ---------------- depthwise causal conv (K=4) + silu ------------------------
__global__ void k_conv(const float* __restrict__ cw, const float* __restrict__ cb) {
    int idx = blockIdx.x * 256 + threadIdx.x;   // over BL_*DI_
    int d = idx & (DI_ - 1);
    int bl = idx >> 9;
    int l = bl & (L_ - 1);
    int b0 = bl - l;
    float s = cb[d];
#pragma unroll
    for (int k = 0; k < K_; k++) {
        int lt = l - (K_ - 1) + k;
        if (lt >= 0) s += g_xz[(size_t)(b0 + lt) * (2 * DI_) + d] * cw[d * K_ + k];
    }
    g_xc[idx] = silu_f(s);
}

// ---------------- fused xproj + dt: 2 rows per block ------------------------
// Phase 1: dbl[row,0:48] = xc[row] @ xw^T (warp w owns tasks 3w..3w+2; each
//          warp stays on ONE row since 12 % 3 == 0). R-cols mirrored to smem.
// Phase 2: dt = softplus(dbl[:, :16] @ dtw^T + dtb) from smem.
__global__ __launch_bounds__(256) void k_xpd(const float* __restrict__ W,
                                             const float* __restrict__ dtw,
                                             const float* __restrict__ dtb) {
    __shared__ float sdbl[2][R_];
    int tid = threadIdx.x;
    int warp = tid >> 5, lane = tid & 31;
    int row0 = blockIdx.x * 2;

    int tg0 = warp * 3;
    int r = tg0 / 12;                    // warp's row (0 or 1)
    int row = row0 + r;
    const float4* ap = (const float4*)(g_xc + (size_t)row * DI_);
    float4 av[4];
#pragma unroll
    for (int j = 0; j < 4; j++) av[j] = ap[j * 32 + lane];

#pragma unroll
    for (int i = 0; i < 3; i++) {
        int tg = tg0 + i;
        int c0 = (tg % 12) * 4;
        float acc[4];
#pragma unroll
        for (int c = 0; c < 4; c++) {
            const float4* wp = (const float4*)(W + (size_t)(c0 + c) * DI_);
            float s = 0.f;
#pragma unroll
            for (int j = 0; j < 4; j++) {
                float4 w = wp[j * 32 + lane];
                s += av[j].x * w.x + av[j].y * w.y + av[j].z * w.z + av[j].w * w.w;
            }
            acc[c] = s;
        }
#pragma unroll
        for (int c = 0; c < 4; c++)
#pragma unroll
            for (int o = 16; o > 0; o >>= 1)
                acc[c] += __shfl_xor_sync(0xffffffffu, acc[c], o);
        if (lane < 4) {
            float v = (lane == 0) ? acc[0] : (lane == 1) ? acc[1]
                     : (lane == 2) ? acc[2] : acc[3];
            g_dbl[row * (R_ + N_) + c0 + lane] = v;
            if (c0 + lane < R_) sdbl[r][c0 + lane] = v;
        }
    }
    __syncthreads();

#pragma unroll
    for (int ii = 0; ii < 4; ii++) {
        int idx = ii * 256 + tid;            // over 2*DI_
        int rr = idx >> 9, d = idx & (DI_ - 1);
        float s = dtb[d];
#pragma unroll
        for (int j = 0; j < R_; j++) s = fmaf(sdbl[rr][j], dtw[d * R_ + j], s);
        g_dt[(row0 + rr) * DI_ + d] = (s > 20.f) ? s : log1pf(expf(s));
    }
}

// ---------------- selective scan: warp per (b,d), lane = n ------------------
// chunk=8 register pipeline: prefetch next chunk's inputs, keep h-chain clean.
__global__ __launch_bounds__(128) void k_scan(const float* __restrict__ Alog,
                                              const float* __restrict__ Cm,
                                              const float* __restrict__ Dv) {
    __shared__ float sm[4][8 * 33];
    int warp = threadIdx.x >> 5;
    int lane = threadIdx.x & 31;
    int w = blockIdx.x * 4 + warp;       // 0..1023
    int n = lane;
    int b = w >> 9;
    int d = w & (DI_ - 1);
    float a = -expf(Alog[d * N_ + n]);
    float c = Cm[d * N_ + n];
    float Ddv = Dv[d];
    float h = 0.f;
    int base = b * L_ * DI_ + d;
    int bbase = b * L_ * (R_ + N_) + R_ + n;
    float* row = sm[warp];

    float dtv[8], xv[8], Bv[8];
#pragma unroll
    for (int j = 0; j < 8; j++) {
        dtv[j] = g_dt[base + j * DI_];
        xv[j]  = g_xc[base + j * DI_];
        Bv[j]  = g_dbl[bbase + j * (R_ + N_)];
    }

    for (int t0 = 0; t0 < L_; t0 += 8) {
        float ndt[8], nx[8], nB[8];
        if (t0 + 8 < L_) {
#pragma unroll
            for (int j = 0; j < 8; j++) {
                int t = t0 + 8 + j;
                ndt[j] = g_dt[base + t * DI_];
                nx[j]  = g_xc[base + t * DI_];
                nB[j]  = g_dbl[bbase + t * (R_ + N_)];
            }
        }
        float p[8];
#pragma unroll
        for (int j = 0; j < 8; j++) {
            float dA = __expf(dtv[j] * a);
            h = fmaf(dA, h, dtv[j] * Bv[j] * xv[j]);
            p[j] = h * c;
            if (n == 0) p[j] = fmaf(Ddv, xv[j], p[j]);
        }
#pragma unroll
        for (int j = 0; j < 8; j++) row[j * 33 + lane] = p[j];
        __syncwarp();
        if (lane < 8) {
            float s0 = 0.f, s1 = 0.f;
#pragma unroll
            for (int k = 0; k < 16; k++) {
                s0 += row[lane * 33 + k];
                s1 += row[lane * 33 + 16 + k];
            }
            g_y[base + (t0 + lane) * DI_] = s0 + s1;
        }
        __syncwarp();
#pragma unroll
        for (int j = 0; j < 8; j++) { dtv[j] = ndt[j]; xv[j] = nx[j]; Bv[j] = nB[j]; }
    }
}

// ---------------- 16-mode forward DFT along L -------------------------------
__global__ void k_dftf() {
    __shared__ float cs[L_], sn[L_];
    int blk = blockIdx.x;                  // 64 = B_*M_*2
    int half = blk & 1;
    int f = (blk >> 1) & (M_ - 1);
    int b = blk >> 5;
    int d = half * 256 + threadIdx.x;
    {
        int kk = (f * threadIdx.x) & (L_ - 1);
        float ang = (6.283185307179586f / L_) * (float)kk;
        cs[threadIdx.x] = cosf(ang);
        sn[threadIdx.x] = sinf(ang);
    }
    __syncthreads();
    float ar = 0.f, ai = 0.f;
    int base = b * L_ * DI_ + d;
    for (int t = 0; t < L_; t++) {
        float xv = g_xc[base + t * DI_];
        ar = fmaf(xv, cs[t], ar);
        ai = fmaf(-xv, sn[t], ai);
    }
    g_xr[(b * M_ + f) * DI_ + d] = ar;
    g_xi[(b * M_ + f) * DI_ + d] = ai;
}

// ---------------- fused inverse DFT + gate ----------------------------------
// idx over BL_*DI_; y = scan_y + irfft16; out = y * silu(z)
__global__ void k_dftig(const float* __restrict__ sr, const float* __restrict__ si) {
    __shared__ float cs[M_], sn[M_];
    int idx = blockIdx.x * 256 + threadIdx.x;
    int bl = idx >> 9;                    // (b*L + t), const per block
    int d = idx & (DI_ - 1);
    int t = bl & (L_ - 1);
    int b = bl >> 8;
    if (threadIdx.x < M_) {
        int kk = (threadIdx.x * t) & (L_ - 1);
        float ang = (6.283185307179586f / L_) * (float)kk;
        cs[threadIdx.x] = cosf(ang);
        sn[threadIdx.x] = sinf(ang);
    }
    __syncthreads();
    float acc = 0.f;
#pragma unroll
    for (int f = 0; f < M_; f++) {
        float xr = g_xr[(b * M_ + f) * DI_ + d];
        float xi = g_xi[(b * M_ + f) * DI_ + d];
        float wr = sr[d * M_ + f];
        float wi = si[d * M_ + f];
        float zr = xr * wr - xi * wi;
        float zi = xr * wi + xi * wr;
        float v = zr * cs[f] - zi * sn[f];
        acc += (f == 0) ? v : 2.f * v;
    }
    float y = g_y[idx] + acc * (1.0f / L_);
    float z = g_xz[(size_t)bl * (2 * DI_) + DI_ + d];
    g_gate[idx] = y * silu_f(z);
}

// ---------------- host driver ------------------------------------------------
static cudaStream_t s2;
static cudaEvent_t ev_fork, ev_join;
static bool s_init = false;

static void run_mixer(const float* in_w, const float* cw, const float* cb,
                      const float* xw, const float* dtw, const float* dtb,
                      const float* Al, const float* Cm, const float* Dv,
                      const float* sr, const float* si,
                      const float* ow, float* outC, int outN, int is_final,
                      float* p_ln, float* p_xz, float* p_gate) {
    // in_proj: [512,1024] = ln[512,256] @ in_w[1024,256]^T
    gemm_db<64, 64, 2, 4><<<dim3(2 * DI_ / 64, BL_ / 64), 256>>>(p_ln, in_w, p_xz, 2 * DI_, D_);
    k_conv<<<BL_ * DI_ / 256, 256>>>(cw, cb);
    // fork: forward DFT runs concurrently with xproj+dt -> scan
    cudaEventRecord(ev_fork, 0);
    cudaStreamWaitEvent(s2, ev_fork, 0);
    k_dftf<<<B_ * M_ * 2, 256, 0, s2>>>();
    cudaEventRecord(ev_join, s2);
    k_xpd<<<BL_ / 2, 256>>>(xw, dtw, dtb);
    k_scan<<<256, 128>>>(Al, Cm, Dv);
    cudaStreamWaitEvent(0, ev_join, 0);
    k_dftig<<<BL_ * DI_ / 256, 256>>>(sr, si);
    if (is_final) {
        gemm_db<128, 128, 2, 4><<<dim3(outN / 128, BL_ / 128), 256>>>(p_gate, ow, outC, outN, DI_);
    } else {
        gemm_db<32, 64, 2, 4><<<dim3(outN / 64, BL_ / 32), 256>>>(p_gate, ow, outC, outN, DI_);
    }
}

extern "C" void kernel_launch(void* const* d_in, const int* in_sizes, int n_in,
                              void* d_out, int out_size) {
    if (!s_init) {
        cudaStreamCreateWithFlags(&s2, cudaStreamNonBlocking);
        cudaEventCreateWithFlags(&ev_fork, cudaEventDisableTiming);
        cudaEventCreateWithFlags(&ev_join, cudaEventDisableTiming);
        s_init = true;
    }
    const float* x       = (const float*)d_in[0];
    const float* ln_w    = (const float*)d_in[1];
    const float* ln_b    = (const float*)d_in[2];
    const float* in_w    = (const float*)d_in[3];
    const float* conv_w  = (const float*)d_in[4];
    const float* conv_b  = (const float*)d_in[5];
    const float* xproj_w = (const float*)d_in[6];
    const float* dt_w    = (const float*)d_in[7];
    const float* dt_b    = (const float*)d_in[8];
    const float* A_log   = (const float*)d_in[9];
    const float* Cmat    = (const float*)d_in[10];
    const float* Dvec    = (const float*)d_in[11];
    const float* spec_r  = (const float*)d_in[12];
    const float* spec_i  = (const float*)d_in[13];
    const float* out_w   = (const float*)d_in[14];
    const float* fln_w   = (const float*)d_in[15];
    const float* fln_b   = (const float*)d_in[16];
    const float* f_in_w  = (const float*)d_in[17];
    const float* f_conv_w  = (const float*)d_in[18];
    const float* f_conv_b  = (const float*)d_in[19];
    const float* f_xproj_w = (const float*)d_in[20];
    const float* f_dt_w    = (const float*)d_in[21];
    const float* f_dt_b    = (const float*)d_in[22];
    const float* f_A_log   = (const float*)d_in[23];
    const float* f_Cmat    = (const float*)d_in[24];
    const float* f_Dvec    = (const float*)d_in[25];
    const float* f_spec_r  = (const float*)d_in[26];
    const float* f_spec_i  = (const float*)d_in[27];
    const float* f_out_w   = (const float*)d_in[28];

    float *p_ln, *p_xz, *p_gate, *p_hid;
    cudaGetSymbolAddress((void**)&p_ln, g_ln);
    cudaGetSymbolAddress((void**)&p_xz, g_xz);
    cudaGetSymbolAddress((void**)&p_gate, g_gate);
    cudaGetSymbolAddress((void**)&p_hid, g_hid);

    for (int i = 0; i < NB_; i++) {
        k_prenorm<<<BL_, D_>>>(x, ln_w + i * D_, ln_b + i * D_, (i == 0) ? 1 : 0);
        run_mixer(in_w + (size_t)i * 2 * DI_ * D_,
                  conv_w + (size_t)i * DI_ * K_,
                  conv_b + (size_t)i * DI_,
                  xproj_w + (size_t)i * (R_ + N_) * DI_,
                  dt_w + (size_t)i * DI_ * R_,
                  dt_b + (size_t)i * DI_,
                  A_log + (size_t)i * DI_ * N_,
                  Cmat + (size_t)i * DI_ * N_,
                  Dvec + (size_t)i * DI_,
                  spec_r + (size_t)i * DI_ * M_,
                  spec_i + (size_t)i * DI_ * M_,
                  out_w + (size_t)i * D_ * DI_,
                  p_hid, D_, 0,
                  p_ln, p_xz, p_gate);
    }
    // final block
    k_prenorm<<<BL_, D_>>>(x, fln_w, fln_b, 0);
    run_mixer(f_in_w, f_conv_w, f_conv_b, f_xproj_w, f_dt_w, f_dt_b,
              f_A_log, f_Cmat, f_Dvec, f_spec_r, f_spec_i,
              f_out_w, (float*)d_out, DOUT_, 1,
              p_ln, p_xz, p_gate);
}